// round 16
// baseline (speedup 1.0000x reference)
#include <cuda_runtime.h>
#include <cuda_fp16.h>
#include <math.h>
#include <stdint.h>

// ===========================================================================
// PixelateDegradation:  out[b,c] = C_{t[b]} @ x0[b,c] @ C_{t[b]}^T
// R16: R15 (fp16 D=Ah@Bh GEMMs, inline-fp32-tap chain) with the two GEMM
// phases FUSED via 2-CTA clusters: cluster = {(mb,nb=0),(mb,nb=1)} supplies
// exactly the Y rows phase2 needs. csz=2 packs perfectly on 148 SMs.
// ===========================================================================

#define TS 20
#define SZ 256
#define NIMG 192

__device__ __half g_Ch[TS][SZ][SZ];
__device__ __half g_Yh[(size_t)NIMG * SZ * SZ];   // Y = C@X (m-major, k-contig)

// ---------------------------------------------------------------------------
// chain_kernel: block = 4 columns of C, thread = row o. 20 sequential steps,
// inline fp32 bicubic taps (floor-exact vs the fp64 numpy build).
// ---------------------------------------------------------------------------
__device__ __forceinline__ float cc1f(float x) {
    const float A = -0.75f;
    return ((A + 2.0f) * x - (A + 3.0f)) * x * x + 1.0f;
}
__device__ __forceinline__ float cc2f(float x) {
    const float A = -0.75f;
    return ((A * x - 5.0f * A) * x + 8.0f * A) * x - 4.0f * A;
}

__global__ void chain_kernel() {
    const int o  = threadIdx.x;
    const int h0 = blockIdx.x * 4;

    __shared__ float c[2][SZ][4];
#pragma unroll
    for (int j = 0; j < 4; j++)
        c[0][o][j] = (o == h0 + j) ? 1.0f : 0.0f;
    __syncthreads();

    int cur = 0;
#pragma unroll 1
    for (int s = 0; s < TS; s++) {
        float4 v = *reinterpret_cast<const float4*>(&c[cur][o][0]);
        __half2 t0 = __halves2half2(__float2half_rn(v.x), __float2half_rn(v.y));
        __half2 t1 = __halves2half2(__float2half_rn(v.z), __float2half_rn(v.w));
        uint2 hs;
        hs.x = *reinterpret_cast<uint32_t*>(&t0);
        hs.y = *reinterpret_cast<uint32_t*>(&t1);
        *reinterpret_cast<uint2*>(&g_Ch[s][o][h0]) = hs;

        if (s == TS - 1) break;

        float ssf = (float)(SZ - s);
        int src = (int)floorf((o + 0.5f) * ssf * (1.0f / 256.0f));
        int smax = (SZ - s) - 1;
        if (src > smax) src = smax;
        if (src < 0) src = 0;
        float x  = ((float)src + 0.5f) * 256.0f / ssf - 0.5f;
        float i0 = floorf(x);
        float tt = x - i0;
        float wf[4] = {cc2f(tt + 1.0f), cc1f(tt), cc1f(1.0f - tt),
                       cc2f(2.0f - tt)};
        int ib = (int)i0 - 1;

        float acc0 = 0.f, acc1 = 0.f, acc2 = 0.f, acc3 = 0.f;
#pragma unroll
        for (int k = 0; k < 4; k++) {
            int col = ib + k;
            if (col < 0) col = 0;
            if (col > SZ - 1) col = SZ - 1;
            float4 cv = *reinterpret_cast<const float4*>(&c[cur][col][0]);
            acc0 += wf[k] * cv.x;
            acc1 += wf[k] * cv.y;
            acc2 += wf[k] * cv.z;
            acc3 += wf[k] * cv.w;
        }
        c[cur ^ 1][o][0] = acc0;
        c[cur ^ 1][o][1] = acc1;
        c[cur ^ 1][o][2] = acc2;
        c[cur ^ 1][o][3] = acc3;
        __syncthreads();
        cur ^= 1;
    }
}

// ---------------------------------------------------------------------------
// GEMM: 128x128 CTA tile, 8 warps (32x64 warp tiles), K-chunk 32,
// double-buffered smem. Per-buffer (80B row pitch): A +0, B +10240;
// buffer stride 20480; total 40960 B.   (byte-identical to R12/R15)
// ---------------------------------------------------------------------------
static constexpr int SMEM_BYTES = 40960;
static constexpr uint32_t T_B  = 10240;
static constexpr uint32_t BUFSTRIDE = 20480;

__device__ __forceinline__ uint32_t smem_to_u32(const void* p) {
    uint32_t a;
    asm("{ .reg .u64 t; cvta.to.shared.u64 t, %1; cvt.u32.u64 %0, t; }"
        : "=r"(a) : "l"(p));
    return a;
}
__device__ __forceinline__ void ldsm_x4(uint32_t r[4], uint32_t addr) {
    asm volatile("ldmatrix.sync.aligned.m8n8.x4.shared.b16 {%0,%1,%2,%3}, [%4];"
                 : "=r"(r[0]), "=r"(r[1]), "=r"(r[2]), "=r"(r[3]) : "r"(addr));
}
__device__ __forceinline__ void mma16816(float d[4], const uint32_t a[4],
                                         const uint32_t b[2]) {
    asm volatile(
        "mma.sync.aligned.m16n8k16.row.col.f32.f16.f16.f32 "
        "{%0,%1,%2,%3}, {%4,%5,%6,%7}, {%8,%9}, {%0,%1,%2,%3};"
        : "+f"(d[0]), "+f"(d[1]), "+f"(d[2]), "+f"(d[3])
        : "r"(a[0]), "r"(a[1]), "r"(a[2]), "r"(a[3]), "r"(b[0]), "r"(b[1]));
}
__device__ __forceinline__ void cp16(uint32_t d, const void* g) {
    asm volatile("cp.async.cg.shared.global [%0], [%1], 16;"
                 :: "r"(d), "l"(g) : "memory");
}
#define CP_COMMIT() asm volatile("cp.async.commit_group;" ::: "memory")
#define CP_WAIT(N)  asm volatile("cp.async.wait_group %0;" :: "n"(N) : "memory")

#define STS128(r0, r1, r2, r3, addr) \
    asm volatile("st.shared.v4.b32 [%0], {%1, %2, %3, %4};" \
        :: "r"(addr), "r"(r0), "r"(r1), "r"(r2), "r"(r3) : "memory")

// pack 8 floats to fp16
__device__ __forceinline__ void pack8_hi(const float v[8], uint32_t hi[4]) {
#pragma unroll
    for (int i = 0; i < 4; i++) {
        __half2 h = __halves2half2(__float2half_rn(v[2 * i]),
                                   __float2half_rn(v[2 * i + 1]));
        hi[i] = *reinterpret_cast<const uint32_t*>(&h);
    }
}

// stage a 128x32 fp16 tile (8KB) via cp.async; 2 cp16 per thread
__device__ __forceinline__ void stage_tile(uint32_t dstBase,
                                           const __half* __restrict__ G,
                                           int rb, int kc, int tid) {
    int r = tid >> 1;                 // 0..127
    int s = (tid & 1) * 2;            // 16B chunk 0 or 2
    uint32_t dst = dstBase + (uint32_t)(r * 80 + s * 16);
    size_t goff = (size_t)(rb + r) * SZ + kc + s * 8;
    cp16(dst,      G + goff);
    cp16(dst + 16, G + goff + 8);
}

// stage B tile from fp32 X with transpose: B[n][k] = X[kc+k][nb+n]
__device__ __forceinline__ void stageB_trans(uint32_t buf,
                                             const float* __restrict__ X,
                                             int nb, int kc, int wid, int lane) {
#pragma unroll
    for (int rep = 0; rep < 2; rep++) {
        int it = wid + rep * 8;        // 16 tasks
        int j0 = (it & 3) * 8;         // k-group of 8
        int n0 = (it >> 2) * 32;       // n-group of 32
        const float* xp = X + (size_t)(kc + j0) * SZ + nb + n0 + lane;
        float v[8];
#pragma unroll
        for (int j = 0; j < 8; j++) v[j] = xp[(size_t)j * SZ];
        uint32_t hi[4];
        pack8_hi(v, hi);
        uint32_t addr = buf + T_B +
            (uint32_t)((n0 + lane) * 80 + (j0 >> 3) * 16);
        STS128(hi[0], hi[1], hi[2], hi[3], addr);
    }
}

__device__ __forceinline__ void compute_chunk(uint32_t buf, int warpm, int warpn,
                                              int lane, float acc[2][8][4]) {
    const uint32_t arow = buf +
        (uint32_t)((warpm * 32 + (lane & 15)) * 80 + ((lane & 16) ? 16 : 0));
    const uint32_t brow = buf + T_B +
        (uint32_t)((warpn * 64 + (lane & 7) + ((lane & 16) ? 8 : 0)) * 80 +
                   ((lane & 8) ? 16 : 0));
#pragma unroll
    for (int K16 = 0; K16 < 2; K16++) {
        uint32_t aH[2][4];
#pragma unroll
        for (int mt = 0; mt < 2; mt++)
            ldsm_x4(aH[mt], arow + (uint32_t)(mt * 16 * 80 + K16 * 32));
        uint32_t bH[4][4];
#pragma unroll
        for (int g = 0; g < 4; g++)
            ldsm_x4(bH[g], brow + (uint32_t)(g * 16 * 80 + K16 * 32));
#pragma unroll
        for (int g = 0; g < 4; g++)
#pragma unroll
            for (int mt = 0; mt < 2; mt++) {
                mma16816(acc[mt][2 * g],     aH[mt], bH[g]);
                mma16816(acc[mt][2 * g + 1], aH[mt], bH[g] + 2);
            }
    }
}

// PH1: A = Ch (cp.async), B = X transposed inline; epilogue packs Y to fp16.
// PH2: A = Yh (cp.async), B = Ch (cp.async); epilogue fp32.
template <bool PH1>
__device__ __forceinline__ void mm_core(
    int mb, int nb,
    const __half* __restrict__ Ah, const __half* __restrict__ Bh,
    const float* __restrict__ Xf,
    float* __restrict__ Of, __half* __restrict__ Oh) {
    extern __shared__ char smem[];
    uint32_t sb = smem_to_u32(smem);

    const int tid   = threadIdx.x;
    const int lane  = tid & 31;
    const int wid   = tid >> 5;
    const int warpm = wid & 3;      // 4 m-tiles of 32
    const int warpn = wid >> 2;     // 2 n-tiles of 64

    float acc[2][8][4];
#pragma unroll
    for (int i = 0; i < 2; i++)
#pragma unroll
        for (int j = 0; j < 8; j++)
#pragma unroll
            for (int q = 0; q < 4; q++) acc[i][j][q] = 0.0f;

    // prologue: stage chunks 0,1
    stage_tile(sb, Ah, mb, 0, tid);
    if (PH1) stageB_trans(sb, Xf, nb, 0, wid, lane);
    else     stage_tile(sb + T_B, Bh, nb, 0, tid);
    CP_COMMIT();
    stage_tile(sb + BUFSTRIDE, Ah, mb, 32, tid);
    if (PH1) stageB_trans(sb + BUFSTRIDE, Xf, nb, 32, wid, lane);
    else     stage_tile(sb + BUFSTRIDE + T_B, Bh, nb, 32, tid);
    CP_COMMIT();

#pragma unroll 1
    for (int c = 0; c < 8; c++) {
        if (c < 7) { CP_WAIT(1); } else { CP_WAIT(0); }
        __syncthreads();
        uint32_t buf = sb + (uint32_t)((c & 1) * BUFSTRIDE);
        compute_chunk(buf, warpm, warpn, lane, acc);
        __syncthreads();
        if (c + 2 < 8) {
            stage_tile(buf, Ah, mb, (c + 2) * 32, tid);
            if (PH1) stageB_trans(buf, Xf, nb, (c + 2) * 32, wid, lane);
            else     stage_tile(buf + T_B, Bh, nb, (c + 2) * 32, tid);
            CP_COMMIT();
        }
    }

    // epilogue
    const int rbase = mb + warpm * 32 + (lane >> 2);
    const int cbase = nb + warpn * 64 + (lane & 3) * 2;
#pragma unroll
    for (int mt = 0; mt < 2; mt++) {
#pragma unroll
        for (int nt = 0; nt < 8; nt++) {
            int col = cbase + nt * 8;
            int r0 = rbase + mt * 16;
            int r1 = r0 + 8;
            float v0 = acc[mt][nt][0], v1 = acc[mt][nt][1];
            float v2 = acc[mt][nt][2], v3 = acc[mt][nt][3];
            if (PH1) {
                __half2 h01 = __halves2half2(__float2half_rn(v0),
                                             __float2half_rn(v1));
                __half2 h23 = __halves2half2(__float2half_rn(v2),
                                             __float2half_rn(v3));
                *reinterpret_cast<__half2*>(Oh + (size_t)r0 * SZ + col) = h01;
                *reinterpret_cast<__half2*>(Oh + (size_t)r1 * SZ + col) = h23;
            } else {
                *reinterpret_cast<float2*>(Of + (size_t)r0 * SZ + col) =
                    make_float2(v0, v1);
                *reinterpret_cast<float2*>(Of + (size_t)r1 * SZ + col) =
                    make_float2(v2, v3);
            }
        }
    }
}

// Fused kernel: 2-CTA cluster = {nb=0, nb=1} for one (image, mb) pair.
// Phase2 tile (mb,nb) needs Y rows mb over all k — exactly the cluster's
// two phase1 outputs.
__global__ void __launch_bounds__(256, 3) __cluster_dims__(2, 1, 1)
fused_kernel(const float* __restrict__ x0, const int* __restrict__ t,
             float* __restrict__ out) {
    int img = blockIdx.z;
    int tb  = __ldg(&t[img / 3]);
    size_t io = (size_t)img * SZ * SZ;

    int mb = blockIdx.y * 128;
    int nb = blockIdx.x * 128;

    // phase1: Y[mb.., nb..] = C[mb..] @ X (cols nb..)
    mm_core<true>(mb, nb, &g_Ch[tb][0][0], nullptr, x0 + io,
                  nullptr, g_Yh + io);

    // make Y visible to the cluster peer (STG -> L2; cp.async.cg reads L2)
    __threadfence();
    asm volatile("barrier.cluster.arrive.aligned;" ::: "memory");
    asm volatile("barrier.cluster.wait.aligned;" ::: "memory");

    // phase2: out[mb.., nb..] = Y[mb..] @ C^T (rows nb..)
    mm_core<false>(mb, nb, g_Yh + io, &g_Ch[tb][0][0], nullptr,
                   out + io, nullptr);
}

// ---------------------------------------------------------------------------
extern "C" void kernel_launch(void* const* d_in, const int* in_sizes, int n_in,
                              void* d_out, int out_size) {
    const float* x0 = (const float*)d_in[0];
    const int*   t  = (const int*)d_in[1];
    float* out      = (float*)d_out;

    chain_kernel<<<SZ / 4, 256>>>();

    cudaFuncSetAttribute(fused_kernel,
                         cudaFuncAttributeMaxDynamicSharedMemorySize, SMEM_BYTES);
    fused_kernel<<<dim3(2, 2, NIMG), 256, SMEM_BYTES>>>(x0, t, out);
}

// round 17
// speedup vs baseline: 1.2112x; 1.2112x over previous
#include <cuda_runtime.h>
#include <cuda_fp16.h>
#include <math.h>
#include <stdint.h>

// ===========================================================================
// PixelateDegradation:  out[b,c] = C_{t[b]} @ x0[b,c] @ C_{t[b]}^T
// R17: R15 structure (fp16 D=Ah@Bh GEMMs, inline-fp32-tap chain), GEMM CTAs
// widened to 512 threads / 16 warps with 32x32 warp tiles -> acc 32 regs,
// 2 CTAs/SM, 32 resident warps (occ 50%) for latency hiding.
// ===========================================================================

#define TS 20
#define SZ 256
#define NIMG 192

__device__ __half g_Ch[TS][SZ][SZ];
__device__ __half g_Yh[(size_t)NIMG * SZ * SZ];   // Y = C@X (m-major, k-contig)

// ---------------------------------------------------------------------------
// chain_kernel: block = 4 columns of C, thread = row o. 20 sequential steps,
// inline fp32 bicubic taps (floor-exact vs the fp64 numpy build).
// ---------------------------------------------------------------------------
__device__ __forceinline__ float cc1f(float x) {
    const float A = -0.75f;
    return ((A + 2.0f) * x - (A + 3.0f)) * x * x + 1.0f;
}
__device__ __forceinline__ float cc2f(float x) {
    const float A = -0.75f;
    return ((A * x - 5.0f * A) * x + 8.0f * A) * x - 4.0f * A;
}

__global__ void chain_kernel() {
    const int o  = threadIdx.x;
    const int h0 = blockIdx.x * 4;

    __shared__ float c[2][SZ][4];
#pragma unroll
    for (int j = 0; j < 4; j++)
        c[0][o][j] = (o == h0 + j) ? 1.0f : 0.0f;
    __syncthreads();

    int cur = 0;
#pragma unroll 1
    for (int s = 0; s < TS; s++) {
        float4 v = *reinterpret_cast<const float4*>(&c[cur][o][0]);
        __half2 t0 = __halves2half2(__float2half_rn(v.x), __float2half_rn(v.y));
        __half2 t1 = __halves2half2(__float2half_rn(v.z), __float2half_rn(v.w));
        uint2 hs;
        hs.x = *reinterpret_cast<uint32_t*>(&t0);
        hs.y = *reinterpret_cast<uint32_t*>(&t1);
        *reinterpret_cast<uint2*>(&g_Ch[s][o][h0]) = hs;

        if (s == TS - 1) break;

        float ssf = (float)(SZ - s);
        int src = (int)floorf((o + 0.5f) * ssf * (1.0f / 256.0f));
        int smax = (SZ - s) - 1;
        if (src > smax) src = smax;
        if (src < 0) src = 0;
        float x  = ((float)src + 0.5f) * 256.0f / ssf - 0.5f;
        float i0 = floorf(x);
        float tt = x - i0;
        float wf[4] = {cc2f(tt + 1.0f), cc1f(tt), cc1f(1.0f - tt),
                       cc2f(2.0f - tt)};
        int ib = (int)i0 - 1;

        float acc0 = 0.f, acc1 = 0.f, acc2 = 0.f, acc3 = 0.f;
#pragma unroll
        for (int k = 0; k < 4; k++) {
            int col = ib + k;
            if (col < 0) col = 0;
            if (col > SZ - 1) col = SZ - 1;
            float4 cv = *reinterpret_cast<const float4*>(&c[cur][col][0]);
            acc0 += wf[k] * cv.x;
            acc1 += wf[k] * cv.y;
            acc2 += wf[k] * cv.z;
            acc3 += wf[k] * cv.w;
        }
        c[cur ^ 1][o][0] = acc0;
        c[cur ^ 1][o][1] = acc1;
        c[cur ^ 1][o][2] = acc2;
        c[cur ^ 1][o][3] = acc3;
        __syncthreads();
        cur ^= 1;
    }
}

// ---------------------------------------------------------------------------
// GEMM: 128x128 CTA tile, 512 threads (16 warps, 32x32 warp tiles), K-chunk
// 32, double-buffered smem. Per-buffer (80B row pitch): A +0, B +10240;
// buffer stride 20480; total 40960 B.
// ---------------------------------------------------------------------------
static constexpr int SMEM_BYTES = 40960;
static constexpr uint32_t T_B  = 10240;
static constexpr uint32_t BUFSTRIDE = 20480;

__device__ __forceinline__ uint32_t smem_to_u32(const void* p) {
    uint32_t a;
    asm("{ .reg .u64 t; cvta.to.shared.u64 t, %1; cvt.u32.u64 %0, t; }"
        : "=r"(a) : "l"(p));
    return a;
}
__device__ __forceinline__ void ldsm_x4(uint32_t r[4], uint32_t addr) {
    asm volatile("ldmatrix.sync.aligned.m8n8.x4.shared.b16 {%0,%1,%2,%3}, [%4];"
                 : "=r"(r[0]), "=r"(r[1]), "=r"(r[2]), "=r"(r[3]) : "r"(addr));
}
__device__ __forceinline__ void mma16816(float d[4], const uint32_t a[4],
                                         const uint32_t b[2]) {
    asm volatile(
        "mma.sync.aligned.m16n8k16.row.col.f32.f16.f16.f32 "
        "{%0,%1,%2,%3}, {%4,%5,%6,%7}, {%8,%9}, {%0,%1,%2,%3};"
        : "+f"(d[0]), "+f"(d[1]), "+f"(d[2]), "+f"(d[3])
        : "r"(a[0]), "r"(a[1]), "r"(a[2]), "r"(a[3]), "r"(b[0]), "r"(b[1]));
}
__device__ __forceinline__ void cp16(uint32_t d, const void* g) {
    asm volatile("cp.async.cg.shared.global [%0], [%1], 16;"
                 :: "r"(d), "l"(g) : "memory");
}
#define CP_COMMIT() asm volatile("cp.async.commit_group;" ::: "memory")
#define CP_WAIT(N)  asm volatile("cp.async.wait_group %0;" :: "n"(N) : "memory")

#define STS128(r0, r1, r2, r3, addr) \
    asm volatile("st.shared.v4.b32 [%0], {%1, %2, %3, %4};" \
        :: "r"(addr), "r"(r0), "r"(r1), "r"(r2), "r"(r3) : "memory")

// pack 8 floats to fp16
__device__ __forceinline__ void pack8_hi(const float v[8], uint32_t hi[4]) {
#pragma unroll
    for (int i = 0; i < 4; i++) {
        __half2 h = __halves2half2(__float2half_rn(v[2 * i]),
                                   __float2half_rn(v[2 * i + 1]));
        hi[i] = *reinterpret_cast<const uint32_t*>(&h);
    }
}

// stage a 128x32 fp16 tile (8KB) via cp.async; 1 cp16 per thread (512 thr)
__device__ __forceinline__ void stage_tile(uint32_t dstBase,
                                           const __half* __restrict__ G,
                                           int rb, int kc, int tid) {
    int r = tid >> 2;                 // 0..127
    int s = tid & 3;                  // 16B chunk 0..3
    uint32_t dst = dstBase + (uint32_t)(r * 80 + s * 16);
    size_t goff = (size_t)(rb + r) * SZ + kc + s * 8;
    cp16(dst, G + goff);
}

// stage B tile from fp32 X with transpose: B[n][k] = X[kc+k][nb+n]
// 16 warps, one task per warp.
__device__ __forceinline__ void stageB_trans(uint32_t buf,
                                             const float* __restrict__ X,
                                             int nb, int kc, int wid, int lane) {
    int j0 = (wid & 3) * 8;            // k-group of 8
    int n0 = (wid >> 2) * 32;          // n-group of 32
    const float* xp = X + (size_t)(kc + j0) * SZ + nb + n0 + lane;
    float v[8];
#pragma unroll
    for (int j = 0; j < 8; j++) v[j] = xp[(size_t)j * SZ];
    uint32_t hi[4];
    pack8_hi(v, hi);
    uint32_t addr = buf + T_B +
        (uint32_t)((n0 + lane) * 80 + (j0 >> 3) * 16);
    STS128(hi[0], hi[1], hi[2], hi[3], addr);
}

// 32x32 warp tile: acc[2 m-subtiles of 16][2 n-groups * 2][4]
__device__ __forceinline__ void compute_chunk(uint32_t buf, int warpm, int warpn,
                                              int lane, float acc[2][4][4]) {
    const uint32_t arow = buf +
        (uint32_t)((warpm * 32 + (lane & 15)) * 80 + ((lane & 16) ? 16 : 0));
    const uint32_t brow = buf + T_B +
        (uint32_t)((warpn * 32 + (lane & 7) + ((lane & 16) ? 8 : 0)) * 80 +
                   ((lane & 8) ? 16 : 0));
#pragma unroll
    for (int K16 = 0; K16 < 2; K16++) {
        uint32_t aH[2][4];
#pragma unroll
        for (int mt = 0; mt < 2; mt++)
            ldsm_x4(aH[mt], arow + (uint32_t)(mt * 16 * 80 + K16 * 32));
        uint32_t bH[2][4];
#pragma unroll
        for (int g = 0; g < 2; g++)
            ldsm_x4(bH[g], brow + (uint32_t)(g * 16 * 80 + K16 * 32));
#pragma unroll
        for (int g = 0; g < 2; g++)
#pragma unroll
            for (int mt = 0; mt < 2; mt++) {
                mma16816(acc[mt][2 * g],     aH[mt], bH[g]);
                mma16816(acc[mt][2 * g + 1], aH[mt], bH[g] + 2);
            }
    }
}

// PH1: A = Ch (cp.async), B = X transposed inline; epilogue packs Y to fp16.
// PH2: A = Yh (cp.async), B = Ch (cp.async); epilogue fp32.
template <bool PH1>
__device__ __forceinline__ void mm_core(
    const __half* __restrict__ Ah, const __half* __restrict__ Bh,
    const float* __restrict__ Xf,
    float* __restrict__ Of, __half* __restrict__ Oh) {
    extern __shared__ char smem[];
    uint32_t sb = smem_to_u32(smem);

    const int tid   = threadIdx.x;
    const int lane  = tid & 31;
    const int wid   = tid >> 5;        // 0..15
    const int warpm = wid & 3;         // 4 m-tiles of 32
    const int warpn = wid >> 2;        // 4 n-tiles of 32
    const int mb    = blockIdx.y * 128;
    const int nb    = blockIdx.x * 128;

    float acc[2][4][4];
#pragma unroll
    for (int i = 0; i < 2; i++)
#pragma unroll
        for (int j = 0; j < 4; j++)
#pragma unroll
            for (int q = 0; q < 4; q++) acc[i][j][q] = 0.0f;

    // prologue: stage chunks 0,1
    stage_tile(sb, Ah, mb, 0, tid);
    if (PH1) stageB_trans(sb, Xf, nb, 0, wid, lane);
    else     stage_tile(sb + T_B, Bh, nb, 0, tid);
    CP_COMMIT();
    stage_tile(sb + BUFSTRIDE, Ah, mb, 32, tid);
    if (PH1) stageB_trans(sb + BUFSTRIDE, Xf, nb, 32, wid, lane);
    else     stage_tile(sb + BUFSTRIDE + T_B, Bh, nb, 32, tid);
    CP_COMMIT();

#pragma unroll 1
    for (int c = 0; c < 8; c++) {
        if (c < 7) { CP_WAIT(1); } else { CP_WAIT(0); }
        __syncthreads();
        uint32_t buf = sb + (uint32_t)((c & 1) * BUFSTRIDE);
        compute_chunk(buf, warpm, warpn, lane, acc);
        __syncthreads();
        if (c + 2 < 8) {
            stage_tile(buf, Ah, mb, (c + 2) * 32, tid);
            if (PH1) stageB_trans(buf, Xf, nb, (c + 2) * 32, wid, lane);
            else     stage_tile(buf + T_B, Bh, nb, (c + 2) * 32, tid);
            CP_COMMIT();
        }
    }

    // epilogue
    const int rbase = mb + warpm * 32 + (lane >> 2);
    const int cbase = nb + warpn * 32 + (lane & 3) * 2;
#pragma unroll
    for (int mt = 0; mt < 2; mt++) {
#pragma unroll
        for (int nt = 0; nt < 4; nt++) {
            int col = cbase + nt * 8;
            int r0 = rbase + mt * 16;
            int r1 = r0 + 8;
            float v0 = acc[mt][nt][0], v1 = acc[mt][nt][1];
            float v2 = acc[mt][nt][2], v3 = acc[mt][nt][3];
            if (PH1) {
                __half2 h01 = __halves2half2(__float2half_rn(v0),
                                             __float2half_rn(v1));
                __half2 h23 = __halves2half2(__float2half_rn(v2),
                                             __float2half_rn(v3));
                *reinterpret_cast<__half2*>(Oh + (size_t)r0 * SZ + col) = h01;
                *reinterpret_cast<__half2*>(Oh + (size_t)r1 * SZ + col) = h23;
            } else {
                *reinterpret_cast<float2*>(Of + (size_t)r0 * SZ + col) =
                    make_float2(v0, v1);
                *reinterpret_cast<float2*>(Of + (size_t)r1 * SZ + col) =
                    make_float2(v2, v3);
            }
        }
    }
}

__global__ void __launch_bounds__(512, 2)
phase1_kernel(const float* __restrict__ x0, const int* __restrict__ t) {
    int img = blockIdx.z;
    int tb  = __ldg(&t[img / 3]);
    size_t io = (size_t)img * SZ * SZ;
    mm_core<true>(&g_Ch[tb][0][0], nullptr, x0 + io, nullptr, g_Yh + io);
}

__global__ void __launch_bounds__(512, 2)
phase2_kernel(float* __restrict__ out, const int* __restrict__ t) {
    int img = blockIdx.z;
    int tb  = __ldg(&t[img / 3]);
    size_t io = (size_t)img * SZ * SZ;
    mm_core<false>(g_Yh + io, &g_Ch[tb][0][0], nullptr, out + io, nullptr);
}

// ---------------------------------------------------------------------------
extern "C" void kernel_launch(void* const* d_in, const int* in_sizes, int n_in,
                              void* d_out, int out_size) {
    const float* x0 = (const float*)d_in[0];
    const int*   t  = (const int*)d_in[1];
    float* out      = (float*)d_out;

    chain_kernel<<<SZ / 4, 256>>>();

    cudaFuncSetAttribute(phase1_kernel,
                         cudaFuncAttributeMaxDynamicSharedMemorySize, SMEM_BYTES);
    cudaFuncSetAttribute(phase2_kernel,
                         cudaFuncAttributeMaxDynamicSharedMemorySize, SMEM_BYTES);
    phase1_kernel<<<dim3(2, 2, NIMG), 512, SMEM_BYTES>>>(x0, t);
    phase2_kernel<<<dim3(2, 2, NIMG), 512, SMEM_BYTES>>>(out, t);
}